// round 16
// baseline (speedup 1.0000x reference)
#include <cuda_runtime.h>
#include <cuda_fp16.h>
#include <math.h>

#define NU 100000
#define NI 50000
#define NN (NU + NI)            // 150000 nodes
#define DIM 64
#define NE 1250000
#define NALL (NN * DIM)         // 9,600,000 elements per buffer
#define NV8 (NALL / 8)          // 1,200,000 8-element vector units

#define SCAN_B 1024
#define NBLK ((NN + SCAN_B - 1) / SCAN_B)   // 147

// Scratch (allocation-free): ~63 MB of __device__ globals.
// s_l = rns .* cur_l (pre-scaled fp16 buffers); sentinel row NN absorbs
// invalid-src edges.
__device__ __align__(16) __half g_s[3][NALL + DIM];
__device__ int   g_degi[NN];      // in-degree
__device__ int   g_rowstart[NN];  // CSR cursor: start -> end (post-fill)
__device__ float g_rns[NN];       // 1/sqrt(deg) or 0
__device__ float g_inv[NN];       // sqrt(deg) or 0
__device__ int   g_ctr;           // global range allocator
__device__ int   g_csr[NE];       // src*64 (or NN*64 sentinel)

// ---------------------------------------------------------------------------
// K0: zero degree, allocator, sentinel rows.
__global__ void k_zero() {
    int i = blockIdx.x * blockDim.x + threadIdx.x;
    if (i < NN) g_degi[i] = 0;
    if (i == 0) g_ctr = 0;
    if (i < DIM) {
        g_s[0][NALL + i] = __float2half_rn(0.0f);
        g_s[1][NALL + i] = __float2half_rn(0.0f);
        g_s[2][NALL + i] = __float2half_rn(0.0f);
    }
}

// K1: in-degree. edge_index is int32 (JAX x64-off). Bounds-guarded.
__global__ void k_deg(const int* __restrict__ ei) {
    int e = blockIdx.x * blockDim.x + threadIdx.x;
    if (e >= NE) return;
    int dst = ei[NE + e];
    if ((unsigned)dst < (unsigned)NN) atomicAdd(&g_degi[dst], 1);
}

// K2: CSR range allocation (shuffle block-scan + one atomic per block);
// precompute rns = 1/sqrt(deg), inv = sqrt(deg) (0 for deg==0).
__global__ void k_alloc() {
    __shared__ int warpsum[32];
    __shared__ int s_base;
    int i = blockIdx.x * SCAN_B + threadIdx.x;
    int lane = threadIdx.x & 31;
    int wid  = threadIdx.x >> 5;
    int v = (i < NN) ? g_degi[i] : 0;
    if (i < NN) {
        g_rns[i] = (v > 0) ? rsqrtf((float)v) : 0.0f;
        g_inv[i] = (v > 0) ? sqrtf((float)v)  : 0.0f;
    }
    int x = v;                                   // inclusive warp scan
    #pragma unroll
    for (int off = 1; off < 32; off <<= 1) {
        int t = __shfl_up_sync(0xFFFFFFFFu, x, off);
        if (lane >= off) x += t;
    }
    if (lane == 31) warpsum[wid] = x;
    __syncthreads();
    if (threadIdx.x < 32) {
        int w = warpsum[threadIdx.x];
        int y = w;
        #pragma unroll
        for (int off = 1; off < 32; off <<= 1) {
            int t = __shfl_up_sync(0xFFFFFFFFu, y, off);
            if (threadIdx.x >= off) y += t;
        }
        warpsum[threadIdx.x] = y - w;            // exclusive
        if (threadIdx.x == 31) s_base = atomicAdd(&g_ctr, y);
    }
    __syncthreads();
    if (i < NN) g_rowstart[i] = s_base + warpsum[wid] + (x - v);
}

// K3: FUSED fill + pre-scale (R14 winner).
__global__ void k_fillscale(const int* __restrict__ ei,
                            const float* __restrict__ uw,
                            const float* __restrict__ iw) {
    int tid = blockIdx.x * blockDim.x + threadIdx.x;
    if (tid < NE) {
        int src = ei[tid];
        int dst = ei[NE + tid];
        if ((unsigned)dst < (unsigned)NN) {      // consistent with deg guard
            int soff = ((unsigned)src < (unsigned)NN) ? (src << 6) : (NN << 6);
            int pos = atomicAdd(&g_rowstart[dst], 1);
            g_csr[pos] = soff;
        }
    }
    if (tid < NV8) {
        int base = tid << 3;                     // 8 elems, one row
        int row  = base >> 6;
        float r = g_rns[row];
        const float* emb = (row < NU) ? &uw[base] : &iw[base - NU * DIM];
        float4 e0 = *reinterpret_cast<const float4*>(emb);
        float4 e1 = *reinterpret_cast<const float4*>(emb + 4);
        __half2 h0 = __floats2half2_rn(r * e0.x, r * e0.y);
        __half2 h1 = __floats2half2_rn(r * e0.z, r * e0.w);
        __half2 h2 = __floats2half2_rn(r * e1.x, r * e1.y);
        __half2 h3 = __floats2half2_rn(r * e1.z, r * e1.w);
        uint4 o;
        o.x = *reinterpret_cast<unsigned*>(&h0);
        o.y = *reinterpret_cast<unsigned*>(&h1);
        o.z = *reinterpret_cast<unsigned*>(&h2);
        o.w = *reinterpret_cast<unsigned*>(&h3);
        *reinterpret_cast<uint4*>(&g_s[0][base]) = o;
    }
}

// Per-edge body, 32B lane: TWO independent uint4 loads (16 halves), half2
// accumulate into set A[8] (or B[8]).
#define EDGE(S, ACC) {                                                     \
    uint4 ra_ = *reinterpret_cast<const uint4*>(&in[(S) + le]);            \
    uint4 rb_ = *reinterpret_cast<const uint4*>(&in[(S) + le + 8]);        \
    ACC[0] = __hadd2(ACC[0], *reinterpret_cast<__half2*>(&ra_.x));         \
    ACC[1] = __hadd2(ACC[1], *reinterpret_cast<__half2*>(&ra_.y));         \
    ACC[2] = __hadd2(ACC[2], *reinterpret_cast<__half2*>(&ra_.z));         \
    ACC[3] = __hadd2(ACC[3], *reinterpret_cast<__half2*>(&ra_.w));         \
    ACC[4] = __hadd2(ACC[4], *reinterpret_cast<__half2*>(&rb_.x));         \
    ACC[5] = __hadd2(ACC[5], *reinterpret_cast<__half2*>(&rb_.y));         \
    ACC[6] = __hadd2(ACC[6], *reinterpret_cast<__half2*>(&rb_.z));         \
    ACC[7] = __hadd2(ACC[7], *reinterpret_cast<__half2*>(&rb_.w)); }

// K4/5: pull layer. 4 lanes per row (32B fp16 each), 8 rows per warp.
// 4-edge unroll => 8 outstanding LDG.128 per thread (2x prior MLP).
__global__ void k_gather(int lin, int lout) {
    int g = blockIdx.x * 64 + (threadIdx.x >> 2);
    if (g >= NN) return;
    int le = (threadIdx.x & 3) << 4;             // 16-half (32B) chunk
    const __half* __restrict__ in = g_s[lin];
    int end = g_rowstart[g];
    int p   = end - g_degi[g];
    __half2 z = __float2half2_rn(0.0f);
    __half2 aA[8] = {z,z,z,z,z,z,z,z};
    __half2 aB[8] = {z,z,z,z,z,z,z,z};
    for (; p + 4 <= end; p += 4) {
        int s0 = g_csr[p],     s1 = g_csr[p + 1];
        int s2 = g_csr[p + 2], s3 = g_csr[p + 3];
        EDGE(s0, aA) EDGE(s1, aB) EDGE(s2, aA) EDGE(s3, aB)
    }
    for (; p < end; ++p) { int s0 = g_csr[p]; EDGE(s0, aA) }
    float r = g_rns[g]; float r2 = r * r;
    unsigned ov[8];
    #pragma unroll
    for (int j = 0; j < 8; j++) {
        float2 fA = __half22float2(aA[j]);
        float2 fB = __half22float2(aB[j]);
        __half2 h = __floats2half2_rn(r2 * (fA.x + fB.x), r2 * (fA.y + fB.y));
        ov[j] = *reinterpret_cast<unsigned*>(&h);
    }
    uint4 o0 = make_uint4(ov[0], ov[1], ov[2], ov[3]);
    uint4 o1 = make_uint4(ov[4], ov[5], ov[6], ov[7]);
    __half* dst = &g_s[lout][(g << 6) + le];
    *reinterpret_cast<uint4*>(dst)     = o0;
    *reinterpret_cast<uint4*>(dst + 8) = o1;
}

// K6: layer-3 gather fused with final average.
// out = 0.25*(emb_fp32 + inv*(s1+s2) + rns*t3); out layout [all;all].
__global__ void k_gather_final(const float* __restrict__ uw,
                               const float* __restrict__ iw,
                               float* __restrict__ out) {
    int g = blockIdx.x * 64 + (threadIdx.x >> 2);
    if (g >= NN) return;
    int le = (threadIdx.x & 3) << 4;
    const __half* __restrict__ in = g_s[2];
    int end = g_rowstart[g];
    int p   = end - g_degi[g];
    __half2 z = __float2half2_rn(0.0f);
    __half2 aA[8] = {z,z,z,z,z,z,z,z};
    __half2 aB[8] = {z,z,z,z,z,z,z,z};
    for (; p + 4 <= end; p += 4) {
        int s0 = g_csr[p],     s1 = g_csr[p + 1];
        int s2 = g_csr[p + 2], s3 = g_csr[p + 3];
        EDGE(s0, aA) EDGE(s1, aB) EDGE(s2, aA) EDGE(s3, aB)
    }
    for (; p < end; ++p) { int s0 = g_csr[p]; EDGE(s0, aA) }

    float r   = g_rns[g];
    float inv = g_inv[g];
    int i = (g << 6) + le;
    const float* emb = (g < NU) ? &uw[i] : &iw[i - NU * DIM];
    uint4 u1a = *reinterpret_cast<const uint4*>(&g_s[1][i]);
    uint4 u1b = *reinterpret_cast<const uint4*>(&g_s[1][i + 8]);
    uint4 u2a = *reinterpret_cast<const uint4*>(&g_s[2][i]);
    uint4 u2b = *reinterpret_cast<const uint4*>(&g_s[2][i + 8]);
    const unsigned* p1 = &u1a.x;   // 8 half2 words across u1a,u1b
    const unsigned* p2 = &u2a.x;
    float res[16];
    #pragma unroll
    for (int j = 0; j < 8; j++) {
        unsigned w1 = (j < 4) ? (&u1a.x)[j] : (&u1b.x)[j - 4];
        unsigned w2 = (j < 4) ? (&u2a.x)[j] : (&u2b.x)[j - 4];
        float2 f1 = __half22float2(*reinterpret_cast<__half2*>(&w1));
        float2 f2 = __half22float2(*reinterpret_cast<__half2*>(&w2));
        float2 tA = __half22float2(aA[j]);
        float2 tB = __half22float2(aB[j]);
        res[2*j]   = 0.25f * (emb[2*j]   + inv * (f1.x + f2.x) + r * (tA.x + tB.x));
        res[2*j+1] = 0.25f * (emb[2*j+1] + inv * (f1.y + f2.y) + r * (tA.y + tB.y));
    }
    (void)p1; (void)p2;
    #pragma unroll
    for (int q = 0; q < 4; q++) {
        float4 v = make_float4(res[4*q], res[4*q+1], res[4*q+2], res[4*q+3]);
        *reinterpret_cast<float4*>(&out[i + 4*q])        = v;
        *reinterpret_cast<float4*>(&out[NALL + i + 4*q]) = v;
    }
}

extern "C" void kernel_launch(void* const* d_in, const int* in_sizes, int n_in,
                              void* d_out, int out_size) {
    const int*   ei = (const int*)d_in[0];      // [2, NE] int32
    const float* uw = (const float*)d_in[1];    // [NU, 64]
    const float* iw = (const float*)d_in[2];    // [NI, 64]
    float*      out = (float*)d_out;            // [2*NALL] floats

    const int T = 256;
    int g_edge = (NE + T - 1) / T;              // covers fill + scale sides
    int g_node = (NN + T - 1) / T;
    int g_gath = (NN + 63) / 64;                // 64 rows per 256-thread block

    k_zero<<<g_node, T>>>();
    k_deg<<<g_edge, T>>>(ei);
    k_alloc<<<NBLK, SCAN_B>>>();
    k_fillscale<<<g_edge, T>>>(ei, uw, iw);

    k_gather<<<g_gath, T>>>(0, 1);              // layer 1: s0 -> s1
    k_gather<<<g_gath, T>>>(1, 2);              // layer 2: s1 -> s2
    k_gather_final<<<g_gath, T>>>(uw, iw, out); // layer 3 + average + dup
}